// round 17
// baseline (speedup 1.0000x reference)
#include <cuda_runtime.h>
#include <cstdint>

#define HID 50
#define NPTS 8192
#define NPARA 5000
#define G 32                         // points per CTA
#define STRIDE 57                    // smem state row stride (floats)
#define NBLK (NPTS / G)              // 256 CTAs
#define THREADS 384                  // 12 warps; warp w owns m-tile w (16 rows)

// shared layout (floats)
#define OFF_S    0                   // state/Z buffer [192][57] = 10944
#define OFF_BF   10944               // B fragments [4][7][7][32] float2 = 12544
#define OFF_WIN  23488               // 3 x 50
#define OFF_BIN  23638
#define OFF_BH   23688               // 4 x 50
#define OFF_WO   23888               // 50 x 2
#define OFF_BO   23988               // 2 (pad 4)
#define OFF_X    23992               // 32 pts x 3
#define OFF_OUT8 24088               // 32 x 8
#define OFF_PART 24344               // 32 x 6
#define SMEM_FLOATS 24536
#define SMEM_BYTES (SMEM_FLOATS * 4) // 98144 B -> 2 CTAs/SM (196KB)

__device__ double g_sums[6];         // zero-init at load; reset after finalize

__device__ __forceinline__ float tf32r(float v) {
    uint32_t u;
    asm("cvt.rna.tf32.f32 %0, %1;" : "=r"(u) : "f"(v));
    return __uint_as_float(u);
}

// tanh(z) and sech^2(z): r = 1/(e^{2z}+1); h = 1-2r; 1-h^2 = 4r(1-r)
__device__ __forceinline__ void tanh_s(float z, float& h, float& s) {
    float e = __expf(2.0f * z);
    float r = __fdividef(1.0f, e + 1.0f);
    h = 1.0f - 2.0f * r;
    s = 4.0f * r * (1.0f - r);
}

// m16n8k8 tf32 mma, fp32 accumulate
__device__ __forceinline__ void mma_tf32(float& c0, float& c1, float& c2, float& c3,
                                         uint32_t a0, uint32_t a1, uint32_t a2, uint32_t a3,
                                         uint32_t b0, uint32_t b1) {
    asm volatile(
        "mma.sync.aligned.m16n8k8.row.col.f32.tf32.tf32.f32 "
        "{%0,%1,%2,%3}, {%4,%5,%6,%7}, {%8,%9}, {%0,%1,%2,%3};"
        : "+f"(c0), "+f"(c1), "+f"(c2), "+f"(c3)
        : "r"(a0), "r"(a1), "r"(a2), "r"(a3), "r"(b0), "r"(b1));
}

__global__ void __launch_bounds__(THREADS, 2) pinn_kernel(
    const float* __restrict__ x,
    const float* __restrict__ W_in, const float* __restrict__ b_in,
    const float* __restrict__ W_hid, const float* __restrict__ b_hid,
    const float* __restrict__ W_out, const float* __restrict__ b_out)
{
    extern __shared__ float sm[];
    const int tid = threadIdx.x;
    const int p0 = blockIdx.x * G;

    // ---- prologue: build per-lane B fragments (tf32, zero-padded)
    // Bf[l][n][k][lane] = {W[l][k*8+tq][n*8+gq], W[l][k*8+tq+4][n*8+gq]}
    for (int idx = tid; idx < 4 * 7 * 7 * 32; idx += THREADS) {
        int l = idx / 1568, r = idx - l * 1568;
        int n = r / 224;   r -= n * 224;
        int k = r / 32;    int ln = r - k * 32;
        int tq_ = ln & 3, gq_ = ln >> 2;
        int kr0 = k * 8 + tq_, kr1 = kr0 + 4, nc = n * 8 + gq_;
        float vx = (kr0 < HID && nc < HID) ? tf32r(W_hid[l * 2500 + kr0 * HID + nc]) : 0.0f;
        float vy = (kr1 < HID && nc < HID) ? tf32r(W_hid[l * 2500 + kr1 * HID + nc]) : 0.0f;
        ((float2*)(sm + OFF_BF))[idx] = make_float2(vx, vy);
    }
    for (int i = tid; i < 150; i += THREADS) sm[OFF_WIN + i] = W_in[i];
    for (int i = tid; i < 50;  i += THREADS) sm[OFF_BIN + i] = b_in[i];
    for (int i = tid; i < 200; i += THREADS) sm[OFF_BH  + i] = b_hid[i];
    for (int i = tid; i < 100; i += THREADS) sm[OFF_WO  + i] = W_out[i];
    if (tid < 2) sm[OFF_BO + tid] = b_out[tid];
    for (int i = tid; i < G * 3; i += THREADS) sm[OFF_X + i] = x[p0 * 3 + i];
    // zero state pad cols 50..56 (A loads/C stores then need no predication)
    for (int i = tid; i < 192 * 7; i += THREADS) {
        int rr = i / 7, cc = 50 + (i - (i / 7) * 7);
        sm[OFF_S + rr * STRIDE + cc] = 0.0f;
    }
    __syncthreads();

    const int lane = tid & 31;
    const int warp = tid >> 5;
    const int gq = lane >> 2;        // mma groupID (0..7)
    const int tq = lane & 3;         // mma threadID_in_group (0..3)

    // ---- input layer: rows r = pt*6+ch, cols j; tf32-rounded state
    for (int idx = tid; idx < G * HID; idx += THREADS) {
        int pt = idx / HID, j = idx - pt * HID;
        float x0 = sm[OFF_X + pt * 3 + 0];
        float x1 = sm[OFF_X + pt * 3 + 1];
        float x2 = sm[OFF_X + pt * 3 + 2];
        float w0 = sm[OFF_WIN + j], w1 = sm[OFF_WIN + 50 + j], w2 = sm[OFF_WIN + 100 + j];
        float z = sm[OFF_BIN + j] + x0 * w0 + x1 * w1 + x2 * w2;
        float h, s; tanh_s(z, h, s);
        float d0 = s * w0, dd0 = -2.0f * h * d0 * w0;
        float d1 = s * w1, dd1 = -2.0f * h * d1 * w1;
        float d2 = s * w2;
        int base = (pt * 6) * STRIDE + j;
        sm[OFF_S + base + 0 * STRIDE] = tf32r(h);
        sm[OFF_S + base + 1 * STRIDE] = tf32r(d0);
        sm[OFF_S + base + 2 * STRIDE] = tf32r(dd0);
        sm[OFF_S + base + 3 * STRIDE] = tf32r(d1);
        sm[OFF_S + base + 4 * STRIDE] = tf32r(dd1);
        sm[OFF_S + base + 5 * STRIDE] = tf32r(d2);
    }
    __syncthreads();

    const int row0 = warp * 16 + gq;   // a0/a2, c0/c1 row
    const int row1 = row0 + 8;         // a1/a3, c2/c3 row
    const int ch0 = row0 % 6;          // bias only on value-channel rows
    const int ch1 = row1 % 6;

    // ---- 4 hidden layers: Z[192,50] = S @ W (+bias on ch==0 rows)
    for (int l = 0; l < 4; l++) {
        const float2* Bf = (const float2*)(sm + OFF_BF) + l * 1568 + lane;
        const float* bl = sm + OFF_BH + l * 50;

        float C[7][4];
        #pragma unroll
        for (int n = 0; n < 7; n++) {
            int col0 = n * 8 + tq * 2, col1 = col0 + 1;
            C[n][0] = (ch0 == 0 && col0 < HID) ? bl[col0] : 0.0f;
            C[n][1] = (ch0 == 0 && col1 < HID) ? bl[col1] : 0.0f;
            C[n][2] = (ch1 == 0 && col0 < HID) ? bl[col0] : 0.0f;
            C[n][3] = (ch1 == 0 && col1 < HID) ? bl[col1] : 0.0f;
        }

        #pragma unroll
        for (int half = 0; half < 2; half++) {
            const int s0 = half * 4;
            const int ns = half ? 3 : 4;              // ksteps 0-3, then 4-6
            uint32_t A[4][4];
            #pragma unroll
            for (int ss = 0; ss < 4; ss++) {
                if (ss < ns) {
                    int ka = (s0 + ss) * 8 + tq;      // ≤51, pad-safe
                    int kb = ka + 4;                  // ≤55, pad-safe
                    A[ss][0] = __float_as_uint(sm[OFF_S + row0 * STRIDE + ka]);
                    A[ss][1] = __float_as_uint(sm[OFF_S + row1 * STRIDE + ka]);
                    A[ss][2] = __float_as_uint(sm[OFF_S + row0 * STRIDE + kb]);
                    A[ss][3] = __float_as_uint(sm[OFF_S + row1 * STRIDE + kb]);
                }
            }
            #pragma unroll
            for (int n = 0; n < 7; n++) {
                #pragma unroll
                for (int ss = 0; ss < 4; ss++) {
                    if (ss < ns) {
                        float2 b = Bf[(n * 7 + (s0 + ss)) * 32];   // LDS.64 coalesced
                        mma_tf32(C[n][0], C[n][1], C[n][2], C[n][3],
                                 A[ss][0], A[ss][1], A[ss][2], A[ss][3],
                                 __float_as_uint(b.x), __float_as_uint(b.y));
                    }
                }
            }
        }
        __syncthreads();   // all warps done reading S before overwrite

        // store Z in place; pad cols receive exact zeros (B pad = 0, bias pad = 0)
        #pragma unroll
        for (int n = 0; n < 7; n++) {
            int col0 = n * 8 + tq * 2;
            sm[OFF_S + row0 * STRIDE + col0]     = C[n][0];
            sm[OFF_S + row0 * STRIDE + col0 + 1] = C[n][1];
            sm[OFF_S + row1 * STRIDE + col0]     = C[n][2];
            sm[OFF_S + row1 * STRIDE + col0 + 1] = C[n][3];
        }
        __syncthreads();

        // elementwise tanh/chain transform in place (cols < 50 only)
        for (int idx = tid; idx < G * HID; idx += THREADS) {
            int pt = idx / HID, col = idx - pt * HID;
            int base = OFF_S + (pt * 6) * STRIDE + col;
            float z   = sm[base + 0 * STRIDE];
            float zx  = sm[base + 1 * STRIDE];
            float zxx = sm[base + 2 * STRIDE];
            float zy  = sm[base + 3 * STRIDE];
            float zyy = sm[base + 4 * STRIDE];
            float zt  = sm[base + 5 * STRIDE];
            float h, s; tanh_s(z, h, s);
            float d0  = s * zx;
            float dd0 = fmaf(-2.0f * h * d0, zx, s * zxx);
            float d1  = s * zy;
            float dd1 = fmaf(-2.0f * h * d1, zy, s * zyy);
            float d2  = s * zt;
            sm[base + 0 * STRIDE] = tf32r(h);
            sm[base + 1 * STRIDE] = tf32r(d0);
            sm[base + 2 * STRIDE] = tf32r(dd0);
            sm[base + 3 * STRIDE] = tf32r(d1);
            sm[base + 4 * STRIDE] = tf32r(dd1);
            sm[base + 5 * STRIDE] = tf32r(d2);
        }
        __syncthreads();
    }

    // ---- output layer: 8 dots per point (channels {val,dxx,dyy,dt} x {u,v})
    if (tid < G * 8) {
        int pt = tid >> 3, q = tid & 7;
        int cidx = q >> 1, o = q & 1;
        int ch = (cidx == 0) ? 0 : (cidx == 1) ? 2 : (cidx == 2) ? 4 : 5;
        const float* cp = sm + OFF_S + (pt * 6 + ch) * STRIDE;
        float acc = (cidx == 0) ? sm[OFF_BO + o] : 0.0f;
        #pragma unroll 2
        for (int k = 0; k < HID; k++)
            acc = fmaf(cp[k], sm[OFF_WO + k * 2 + o], acc);
        sm[OFF_OUT8 + pt * 8 + q] = acc;
    }
    __syncthreads();

    if (tid < G) {
        const float* o8 = sm + OFF_OUT8 + tid * 8;
        float u   = o8[0], v   = o8[1];
        float uxx = o8[2], vxx = o8[3];
        float uyy = o8[4], vyy = o8[5];
        float ut  = o8[6], vt  = o8[7];
        float Q  = u * u + v * v;
        float A1 = vt - 0.5f * uxx - 0.5f * vyy - Q * u + v;
        float A2 = ut + 0.5f * vxx - 0.5f * uyy + Q * v + u;
        float B1 = uyy, B2 = vyy;
        float C1 = Q * v, C2 = Q * u;
        float* pp = sm + OFF_PART + tid * 6;
        pp[0] = A1 * A1 + A2 * A2;
        pp[1] = B1 * B1 + B2 * B2;
        pp[2] = C1 * C1 + C2 * C2;
        pp[3] = A2 * B2 - A1 * B1;
        pp[4] = A1 * C1 + A2 * C2;
        pp[5] = B1 * C1 - B2 * C2;
    }
    __syncthreads();

    if (tid < 6) {
        double s = 0.0;
        #pragma unroll
        for (int p = 0; p < G; p++)
            s += (double)sm[OFF_PART + p * 6 + tid];
        atomicAdd(&g_sums[tid], s);
    }
}

__global__ void finalize_kernel(const float* __restrict__ para, float* __restrict__ out) {
    int p = blockIdx.x * blockDim.x + threadIdx.x;
    if (p < NPARA) {
        double a = (double)para[p * 3 + 0];
        double c = (double)para[p * 3 + 2];
        double r = g_sums[0]
                 + 0.25 * a * a * g_sums[1]
                 + c * c * g_sums[2]
                 + a * g_sums[3]
                 - 2.0 * c * g_sums[4]
                 + a * c * g_sums[5];
        out[p] = (float)(r * (1.0 / (double)NPTS));
    }
}

__global__ void reset_kernel() {
    if (threadIdx.x < 6) g_sums[threadIdx.x] = 0.0;
}

extern "C" void kernel_launch(void* const* d_in, const int* in_sizes, int n_in,
                              void* d_out, int out_size) {
    const float* x     = (const float*)d_in[0];
    const float* para  = (const float*)d_in[1];
    const float* W_in  = (const float*)d_in[2];
    const float* b_in  = (const float*)d_in[3];
    const float* W_hid = (const float*)d_in[4];
    const float* b_hid = (const float*)d_in[5];
    const float* W_out = (const float*)d_in[6];
    const float* b_out = (const float*)d_in[7];
    float* out = (float*)d_out;

    cudaFuncSetAttribute(pinn_kernel, cudaFuncAttributeMaxDynamicSharedMemorySize, SMEM_BYTES);
    pinn_kernel<<<NBLK, THREADS, SMEM_BYTES>>>(
        x, W_in, b_in, W_hid, b_hid, W_out, b_out);
    finalize_kernel<<<(NPARA + 255) / 256, 256>>>(para, out);
    reset_kernel<<<1, 32>>>();
}